// round 6
// baseline (speedup 1.0000x reference)
#include <cuda_runtime.h>
#include <math.h>

#define NN    50000
#define FI    20
#define HIDD  500
#define NOUT  2
#define NPAIR 210            // upper-triangular (incl. diag) pairs of 20
#define BN_EPS 1e-5f
#define CH    250            // rows per block in k_tail (200 blocks exactly)
#define NB    (NN / CH)      // 200

// ---- scratch (__device__ globals, zero-initialized; self-cleaning) ----
static __device__ int    g_deg[NN];            // edge count (self-loop in prepX)
static __device__ float  g_dinv[NN];
static __device__ float4 g_Xs4[NN * 5];        // Xs = dinv[n] * X[n]
static __device__ float4 g_P4[NN * 5];         // P[c] = sum_{r->c} Xs[r]
static __device__ double g_m[FI];              // column sums of aggX
static __device__ double g_G[NPAIR];           // upper-tri Gram aggX^T aggX
static __device__ float  g_M2[FI * NOUT];      // folded 20x2 head matrix
static __device__ float  g_C[NOUT];            // folded bias
// grid-barrier state (restored to 0 every call)
static __device__ int          g_c1;
static __device__ int          g_c2;
static __device__ volatile int g_rel;

// K1: in-degree histogram over col (int4 loads)
__global__ void __launch_bounds__(256) k_deg(const int* __restrict__ col, int E) {
    int t = blockIdx.x * blockDim.x + threadIdx.x;
    int e = 4 * t;
    if (e + 3 < E) {
        int4 c = *(const int4*)(col + e);
        atomicAdd(&g_deg[c.x], 1);
        atomicAdd(&g_deg[c.y], 1);
        atomicAdd(&g_deg[c.z], 1);
        atomicAdd(&g_deg[c.w], 1);
    } else {
        for (int k = e; k < E; k++) atomicAdd(&g_deg[col[k]], 1);
    }
}

// K2: dinv = rsqrt(cnt+1); Xs[n] = dinv[n]*X[n]; reset g_deg (self-clean)
__global__ void __launch_bounds__(256) k_prepX(const float* __restrict__ X) {
    int n = blockIdx.x * blockDim.x + threadIdx.x;
    if (n >= NN) return;
    float d = rsqrtf((float)(g_deg[n] + 1));
    g_deg[n] = 0;
    g_dinv[n] = d;
    const float4* xr = (const float4*)(X + n * FI);
#pragma unroll
    for (int k = 0; k < 5; k++) {
        float4 v = xr[k];
        v.x *= d; v.y *= d; v.z *= d; v.w *= d;
        g_Xs4[n * 5 + k] = v;
    }
}

// K3: edge scatter: P[c] += Xs[r]   (5x red.global.add.v4.f32 per edge)
__global__ void __launch_bounds__(256) k_scatter(const int* __restrict__ ei, int E) {
    int e = blockIdx.x * blockDim.x + threadIdx.x;
    if (e >= E) return;
    int r = ei[e];
    int c = ei[E + e];
    const float4* __restrict__ src = g_Xs4 + r * 5;
    float4* dst = g_P4 + c * 5;
#pragma unroll
    for (int k = 0; k < 5; k++) {
        float4 v = __ldg(src + k);
        asm volatile("red.global.add.v4.f32 [%0], {%1, %2, %3, %4};"
                     :: "l"(dst + k), "f"(v.x), "f"(v.y), "f"(v.z), "f"(v.w)
                     : "memory");
    }
}

// K4 (persistent, 200 blocks co-resident): stats -> grid barrier ->
//    prep (block 0) -> release -> final. aggX never touches global memory.
__global__ void __launch_bounds__(256, 2) k_tail(
                       const float* __restrict__ W,      // gcn_W  [20,500]
                       const float* __restrict__ b,      // gcn_b  [500]
                       const float* __restrict__ gamma,  // [500]
                       const float* __restrict__ beta,   // [500]
                       const float* __restrict__ W2,     // lin_W  [500,2]
                       const float* __restrict__ lb,     // lin_b  [2]
                       float* __restrict__ out) {        // [NN*2 | 500 rsu]
    __shared__ float  s[CH * FI];        // 20 KB: this block's aggX chunk
    __shared__ float  sS[HIDD], sT[HIDD];
    __shared__ float  sGf[NPAIR];
    __shared__ double smm[FI];
    __shared__ float  sRed[42 * 6];
    __shared__ float  sMC[FI * NOUT + NOUT];
    int t = threadIdx.x;                 // 256 threads
    int bid = blockIdx.x;
    int n0 = bid * CH;

    // ---- Phase A: finalize chunk aggX = dinv*(P+Xs) into shared; zero P4
    for (int k = t; k < CH * 5; k += 256) {
        int n = n0 + k / 5;
        int idx = n * 5 + (k % 5);
        float d = g_dinv[n];
        float4 p = g_P4[idx];
        float4 x = g_Xs4[idx];
        float4 a = make_float4(d * (p.x + x.x), d * (p.y + x.y),
                               d * (p.z + x.z), d * (p.w + x.w));
        g_P4[idx] = make_float4(0.f, 0.f, 0.f, 0.f);   // self-clean
        ((float4*)s)[k] = a;
    }
    __syncthreads();

    // ---- Phase B: fp32 stat partials, double-atomic combine
    if (t < FI) {
        float a0 = 0.f, a1 = 0.f;
        for (int n = 0; n < CH; n += 2) {
            a0 += s[n * FI + t];
            a1 += s[(n + 1) * FI + t];
        }
        atomicAdd(&g_m[t], (double)(a0 + a1));
    } else if (t < FI + NPAIR) {
        int p = t - FI, i = 0;
        while (p >= FI - i) { p -= FI - i; i++; }
        int j = i + p;
        float a0 = 0.f, a1 = 0.f;
        for (int n = 0; n < CH; n += 2) {
            a0 += s[n * FI + i] * s[n * FI + j];
            a1 += s[(n + 1) * FI + i] * s[(n + 1) * FI + j];
        }
        atomicAdd(&g_G[t - FI], (double)(a0 + a1));
    }

    // ---- Grid barrier: arrive; block 0 preps; others await release
    __threadfence();
    __syncthreads();
    if (bid == 0) {
        if (t == 0) {
            atomicAdd(&g_c1, 1);
            while (atomicAdd(&g_c1, 0) < NB) { }
        }
        __syncthreads();
        __threadfence();
        // stage stats to shared; self-clean g_m/g_G
        if (t < FI)    { smm[t] = g_m[t];         g_m[t] = 0.0; }
        if (t < NPAIR) { sGf[t] = (float)g_G[t];  g_G[t] = 0.0; }
        __syncthreads();

        // per-feature BN fold + rsu_embedding (node 0 row lives in s[0..19])
        for (int f = t; f < HIDD; f += 256) {
            float w[FI];
#pragma unroll
            for (int i2 = 0; i2 < FI; i2++) w[i2] = W[i2 * HIDD + f];
            float bf = b[f];
            double su = 0.0;
#pragma unroll
            for (int i2 = 0; i2 < FI; i2++) su += smm[i2] * (double)w[i2];
            float suf = (float)su;
            float mean = (suf + (float)NN * bf) * (1.f / (float)NN);
            float q = 0.f;
            int p = 0;
#pragma unroll
            for (int i2 = 0; i2 < FI; i2++) {
                q += sGf[p++] * w[i2] * w[i2];
#pragma unroll
                for (int j2 = i2 + 1; j2 < FI; j2++)
                    q += 2.f * sGf[p++] * w[i2] * w[j2];
            }
            float sumsq_over_n = q * (1.f / (float)NN)
                               + 2.f * bf * suf * (1.f / (float)NN) + bf * bf;
            float var = sumsq_over_n - mean * mean;
            float sc = gamma[f] * rsqrtf(var + BN_EPS);
            float tt = beta[f] - mean * sc;
            sS[f] = sc; sT[f] = tt;
            float u0 = 0.f;
#pragma unroll
            for (int i2 = 0; i2 < FI; i2++) u0 += s[i2] * w[i2];
            out[NN * NOUT + f] = (u0 + bf) * sc + tt;
        }
        __syncthreads();

        // fold M2/C: 42 outputs x 6 partial threads
        if (t < 42 * 6) {
            int o = t / 6, part = t % 6;
            int f0 = part * 84;
            int f1 = (f0 + 84 < HIDD) ? f0 + 84 : HIDD;
            float acc = 0.f;
            if (o < FI * NOUT) {
                int i2 = o / NOUT, oo = o % NOUT;
                for (int f = f0; f < f1; f++)
                    acc += W[i2 * HIDD + f] * sS[f] * W2[f * NOUT + oo];
            } else {
                int oo = o - FI * NOUT;
                for (int f = f0; f < f1; f++)
                    acc += (b[f] * sS[f] + sT[f]) * W2[f * NOUT + oo];
            }
            sRed[t] = acc;
        }
        __syncthreads();
        if (t < 42) {
            float acc = 0.f;
#pragma unroll
            for (int k = 0; k < 6; k++) acc += sRed[t * 6 + k];
            if (t < FI * NOUT) g_M2[t] = acc;
            else               g_C[t - FI * NOUT] = acc + lb[t - FI * NOUT];
        }
        __threadfence();
        __syncthreads();
        if (t == 0) g_rel = 1;
    } else {
        if (t == 0) {
            atomicAdd(&g_c1, 1);
            while (g_rel == 0) { }
        }
        __syncthreads();
        __threadfence();
    }

    // ---- Final: per-node head from shared chunk
    if (t < FI * NOUT) sMC[t] = g_M2[t];
    else if (t < FI * NOUT + NOUT) sMC[t] = g_C[t - FI * NOUT];
    __syncthreads();

    float2* out2 = (float2*)out;
    for (int row = t; row < CH; row += 256) {
        float p0 = sMC[FI * NOUT], p1 = sMC[FI * NOUT + 1];
        const float* ar = s + row * FI;
#pragma unroll
        for (int k = 0; k < FI; k++) {
            float v = ar[k];
            p0 += v * sMC[k * NOUT];
            p1 += v * sMC[k * NOUT + 1];
        }
        float l0 = fmaxf(p0, 0.f), l1 = fmaxf(p1, 0.f);
        float mx = fmaxf(l0, l1);
        float e0 = expf(l0 - mx), e1 = expf(l1 - mx);
        float inv = 1.f / (e0 + e1);
        out2[n0 + row] = make_float2(e0 * inv, e1 * inv);
    }

    // ---- Cleanup barrier state (last arriver restores zeros)
    __syncthreads();
    if (t == 0) {
        __threadfence();
        int v = atomicAdd(&g_c2, 1);
        if (v == NB - 1) {
            g_c1 = 0;
            g_c2 = 0;
            g_rel = 0;
            __threadfence();
        }
    }
}

extern "C" void kernel_launch(void* const* d_in, const int* in_sizes, int n_in,
                              void* d_out, int out_size) {
    const float* X     = (const float*)d_in[0];   // node_feature [50000,20]
    const int*   ei    = (const int*)  d_in[1];   // edge_index   [2,E]
    const float* gcnW  = (const float*)d_in[2];   // [20,500]
    const float* gcnB  = (const float*)d_in[3];   // [500]
    const float* gamma = (const float*)d_in[4];   // [500]
    const float* beta  = (const float*)d_in[5];   // [500]
    const float* linW  = (const float*)d_in[6];   // [500,2]
    const float* linB  = (const float*)d_in[7];   // [2]
    float* out = (float*)d_out;                   // [NN*2 action_prob][500 rsu]

    int E = in_sizes[1] / 2;
    int nb  = (NN + 255) / 256;
    int eb  = (E + 255) / 256;
    int eb4 = (E / 4 + 255) / 256 + 1;

    k_deg<<<eb4, 256>>>(ei + E, E);
    k_prepX<<<nb, 256>>>(X);
    k_scatter<<<eb, 256>>>(ei, E);
    k_tail<<<NB, 256>>>(gcnW, gcnB, gamma, beta, linW, linB, out);
}